// round 14
// baseline (speedup 1.0000x reference)
#include <cuda_runtime.h>
#include <cuda_fp16.h>

#define NN 50000
#define NE 600000
#define EMB 128
#define TDIM 32
#define RAW 32

// ---------------- scratch (static device globals; no allocation) ----------------
static __device__ __align__(16) __half g_Ah[NN * EMB];   // A hi (fp16)
static __device__ __align__(16) __half g_Al[NN * EMB];   // A residual (fp16)
static __device__ __align__(16) __half g_B0h[NN * EMB];  // h (conv even), fp16
static __device__ __align__(16) __half g_B1h[NN * EMB];  // h (conv odd), fp16
static __device__ float g_w64[4 * 64];                   // eW @ a_edge per conv
static __device__ __align__(16) __half g_Wh16[4 * EMB * EMB];  // W fp16, [conv][k][n]
static __device__ int   g_deg[NN];
static __device__ int   g_rowptr[NN + 1];
static __device__ int   g_cur[NN];
static __device__ int   g_bsum[64];
static __device__ int   g_boff[64];
static __device__ int   g_scanCnt;
static __device__ volatile int g_scanFlag;
static __device__ unsigned short g_src16[NE];
static __device__ float g_escA[NE];
static __device__ float g_escB[NE];
static __device__ float g_ss0[NN], g_sd0[NN], g_ss1[NN], g_sd1[NN];

// ---------------- PTX helpers ----------------
__device__ __forceinline__ unsigned smem_u32(const void* p) {
    unsigned r;
    asm("{ .reg .u64 t; cvta.to.shared.u64 t, %1; cvt.u32.u64 %0, t; }" : "=r"(r) : "l"(p));
    return r;
}
__device__ __forceinline__ void ldm4(unsigned* r, unsigned addr) {
    asm volatile("ldmatrix.sync.aligned.m8n8.x4.shared.b16 {%0,%1,%2,%3}, [%4];"
                 : "=r"(r[0]), "=r"(r[1]), "=r"(r[2]), "=r"(r[3]) : "r"(addr));
}
__device__ __forceinline__ void ldm4t(unsigned* r, unsigned addr) {
    asm volatile("ldmatrix.sync.aligned.m8n8.x4.trans.shared.b16 {%0,%1,%2,%3}, [%4];"
                 : "=r"(r[0]), "=r"(r[1]), "=r"(r[2]), "=r"(r[3]) : "r"(addr));
}
__device__ __forceinline__ void mma_f16(float* c, const unsigned* a, unsigned b0, unsigned b1) {
    asm volatile("mma.sync.aligned.m16n8k16.row.col.f32.f16.f16.f32 "
                 "{%0,%1,%2,%3}, {%4,%5,%6,%7}, {%8,%9}, {%0,%1,%2,%3};"
                 : "+f"(c[0]), "+f"(c[1]), "+f"(c[2]), "+f"(c[3])
                 : "r"(a[0]), "r"(a[1]), "r"(a[2]), "r"(a[3]), "r"(b0), "r"(b1));
}
__device__ __forceinline__ void cp16(unsigned dst, const void* src) {
    asm volatile("cp.async.cg.shared.global [%0], [%1], 16;" :: "r"(dst), "l"(src));
}

// ---------------- root kernel: w64 + fp16 W + zero deg/cur/scan state -------------
#define PRE_W64 256
#define PRE_W (4 * EMB * EMB)
__global__ void precompute_k(const float* __restrict__ eW, const float* __restrict__ aedge,
                             const float* __restrict__ W) {
    int idx = blockIdx.x * blockDim.x + threadIdx.x;
    if (idx == 0) { g_scanCnt = 0; g_scanFlag = 0; }
    if (idx < PRE_W64) {
        int c = idx >> 6, j = idx & 63;
        const float* ew = eW + (c * 64 + j) * EMB;
        const float* ae = aedge + c * EMB;
        float s = 0.f;
        #pragma unroll 8
        for (int f = 0; f < EMB; f++) s = fmaf(ew[f], ae[f], s);
        g_w64[idx] = s;
    } else if (idx < PRE_W64 + PRE_W) {
        int i = idx - PRE_W64;
        g_Wh16[i] = __float2half_rn(W[i]);
    } else {
        int i = idx - PRE_W64 - PRE_W;
        if (i < NN) { g_deg[i] = 0; g_cur[i] = 0; }
    }
}

// ---------------- A split: layer 1 (gather emb + split fp16 hi/lo) ----------------
__global__ void splitA_emb_k(const int* __restrict__ ids, const float* __restrict__ emb) {
    int i = blockIdx.x * blockDim.x + threadIdx.x;
    if (i >= NN * 32) return;
    int v = i >> 5, c = i & 31;
    float4 x = ((const float4*)emb)[(size_t)__ldg(&ids[v]) * 32 + c];
    __half h0 = __float2half_rn(x.x), h1 = __float2half_rn(x.y);
    __half h2 = __float2half_rn(x.z), h3 = __float2half_rn(x.w);
    uint2 H, L;
    *(__half2*)&H.x = __half2(h0, h1);
    *(__half2*)&H.y = __half2(h2, h3);
    *(__half2*)&L.x = __half2(__float2half_rn(x.x - __half2float(h0)),
                              __float2half_rn(x.y - __half2float(h1)));
    *(__half2*)&L.y = __half2(__float2half_rn(x.z - __half2float(h2)),
                              __float2half_rn(x.w - __half2float(h3)));
    *(uint2*)&g_Ah[(size_t)v * EMB + c * 4] = H;
    *(uint2*)&g_Al[(size_t)v * EMB + c * 4] = L;
}

// ---------------- CSR build (only edges whose type matches dst's node type) ------
__global__ void hist_k(const int* __restrict__ ei, const int* __restrict__ etype,
                       const int* __restrict__ ntype) {
    int e = blockIdx.x * blockDim.x + threadIdx.x;
    if (e >= NE) return;
    int dst = ei[NE + e];
    int req = (__ldg(&ntype[dst]) == 0) ? 1 : 0;
    if (etype[e] == req) atomicAdd(&g_deg[dst], 1);
}

// fused scan1+scan2+scan3 (49 co-resident blocks; last block scans block sums)
__global__ void scanF_k() {
    __shared__ int ws[32];
    __shared__ int s_last;
    int tid = threadIdx.x, lane = tid & 31, wid = tid >> 5;
    int i = blockIdx.x * 1024 + tid;
    int v = (i < NN) ? g_deg[i] : 0;
    int x = v;
    #pragma unroll
    for (int o = 1; o < 32; o <<= 1) {
        int y = __shfl_up_sync(0xffffffffu, x, o);
        if (lane >= o) x += y;
    }
    if (lane == 31) ws[wid] = x;
    __syncthreads();
    if (wid == 0) {
        int s = ws[lane];
        #pragma unroll
        for (int o = 1; o < 32; o <<= 1) {
            int y = __shfl_up_sync(0xffffffffu, s, o);
            if (lane >= o) s += y;
        }
        ws[lane] = s;
    }
    __syncthreads();
    int incl = x + (wid > 0 ? ws[wid - 1] : 0);
    int myexc = incl - v;
    if (tid == 1023) g_bsum[blockIdx.x] = incl;
    __threadfence();
    if (tid == 0) s_last = (atomicAdd(&g_scanCnt, 1) == (int)gridDim.x - 1);
    __syncthreads();
    if (s_last) {
        int bv = 0, bx = 0;
        if (tid < 64) {
            bv = (tid < (int)gridDim.x) ? g_bsum[tid] : 0;
            bx = bv;
            #pragma unroll
            for (int o = 1; o < 32; o <<= 1) {
                int y = __shfl_up_sync(0xffffffffu, bx, o);
                if (lane >= o) bx += y;
            }
            if (lane == 31) ws[wid] = bx;
        }
        __syncthreads();
        if (tid < 64) {
            int incl2 = bx + (tid >= 32 ? ws[0] : 0);
            g_boff[tid] = incl2 - bv;
            if (tid == 63) g_rowptr[NN] = incl2;
        }
        __threadfence();
        __syncthreads();
        if (tid == 0) g_scanFlag = 1;
    }
    if (tid == 0) {
        while (g_scanFlag == 0) __nanosleep(64);
    }
    __syncthreads();
    __threadfence();
    if (i < NN) g_rowptr[i] = myexc + g_boff[blockIdx.x];
}

__global__ void scatter_k(const int* __restrict__ ei, const int* __restrict__ etype,
                          const int* __restrict__ ntype,
                          const float* __restrict__ eattr, const float* __restrict__ t,
                          const float* __restrict__ timew, const float* __restrict__ timeb) {
    int e = blockIdx.x * blockDim.x + threadIdx.x;
    if (e >= NE) return;
    int dst = ei[NE + e];
    int user = (__ldg(&ntype[dst]) == 0) ? 1 : 0;
    if (etype[e] != user) return;
    int src = ei[e];
    int pos = g_rowptr[dst] + atomicAdd(&g_cur[dst], 1);
    g_src16[pos] = (unsigned short)src;

    const float* w1 = g_w64 + user * 64;
    const float* w2 = g_w64 + (2 + user) * 64;
    float tv = t[e];
    float e1 = 0.f, e2 = 0.f;
    #pragma unroll 8
    for (int j = 0; j < TDIM; j++) {
        float te = __cosf(fmaf(tv, timew[j], timeb[j]));
        e1 = fmaf(te, w1[j], e1);
        e2 = fmaf(te, w2[j], e2);
    }
    const float4* ar = (const float4*)(eattr + (size_t)e * RAW);
    #pragma unroll
    for (int q = 0; q < 8; q++) {
        float4 av = ar[q];
        int j = 32 + q * 4;
        e1 = fmaf(av.x, w1[j], e1);     e1 = fmaf(av.y, w1[j + 1], e1);
        e1 = fmaf(av.z, w1[j + 2], e1); e1 = fmaf(av.w, w1[j + 3], e1);
        e2 = fmaf(av.x, w2[j], e2);     e2 = fmaf(av.y, w2[j + 1], e2);
        e2 = fmaf(av.z, w2[j + 2], e2); e2 = fmaf(av.w, w2[j + 3], e2);
    }
    g_escA[pos] = e1;
    g_escB[pos] = e2;
}

// ---------------- persistent fp16 2-term GEMM, W fragments in REGISTERS ----------
// 128 threads (4 warps). Tile M=32, N=128. W ldm4t hoisted out of the tile loop:
// [8 ks][2 nt16][4] = 64 regs/thread. Mainloop per ks: 4 A ldm4 + 16 mma, zero W smem.
#define BPAD 136
#define MT 32
#define NTILES ((NN + MT - 1) / MT)    // 1563
#define GEMM_GRID_X 222                // x2 -> 444 CTAs -> 3/SM
#define WBYTES (128 * BPAD * 2)        // 34816
#define ABYTES (MT * BPAD * 2)         // 8704
#define SMEM_RED_OFF (WBYTES + 4 * ABYTES)
#define GEMM_SMEM (WBYTES + 4 * ABYTES + 1280)

__global__ void __launch_bounds__(128, 3) gemm_mma_k(const float* __restrict__ asrc,
                                                     const float* __restrict__ adst,
                                                     int convBase) {
    extern __shared__ __align__(16) char smraw[];
    __half* Wh_s = (__half*)smraw;
    float* sredS = (float*)(smraw + SMEM_RED_OFF);        // [4][32]
    float* sredD = sredS + 128;                           // [4][32]
    unsigned sbase = smem_u32(smraw);

    int conv = convBase + blockIdx.z;
    __half* Bout = blockIdx.z ? g_B1h : g_B0h;
    float* ssArr = blockIdx.z ? g_ss1 : g_ss0;
    float* sdArr = blockIdx.z ? g_sd1 : g_sd0;
    int tid = threadIdx.x;
    int lane = tid & 31, warp = tid >> 5;
    int nbase = warp * 32;

    const uint4* Whg = (const uint4*)(g_Wh16 + (size_t)conv * EMB * EMB);
    for (int i = tid; i < 2048; i += 128) {
        int r = i >> 4, c = (i & 15) * 8;
        *(uint4*)&Wh_s[r * BPAD + c] = Whg[i];
    }

    const float* aS = asrc + (size_t)conv * EMB;
    const float* aD = adst + (size_t)conv * EMB;
    float w0s[4], w1s[4], w0d[4], w1d[4];
    #pragma unroll
    for (int nt = 0; nt < 4; nt++) {
        int col = nbase + nt * 8 + (lane & 3) * 2;
        w0s[nt] = aS[col]; w1s[nt] = aS[col + 1];
        w0d[nt] = aD[col]; w1d[nt] = aD[col + 1];
    }

    unsigned lbase = ((unsigned)((lane & 15) * BPAD + 8 * (lane >> 4))) * 2;
    unsigned aW = sbase + lbase + (unsigned)nbase * 2;

    // hoist ALL W fragments into registers (W is stationary across tiles)
    __syncthreads();
    unsigned bhW[8][2][4];
    #pragma unroll
    for (int ks = 0; ks < 8; ks++)
        #pragma unroll
        for (int nt16 = 0; nt16 < 2; nt16++)
            ldm4t(bhW[ks][nt16], aW + (unsigned)(ks * 16 * BPAD + nt16 * 16) * 2);

    auto cpA = [&](int tile, int b) {
        unsigned dbase = sbase + WBYTES + (unsigned)b * 2u * ABYTES;
        #pragma unroll
        for (int ii = 0; ii < 8; ii++) {
            int i = tid + ii * 128;
            int half_ = i >> 9;
            int j = i & 511;
            int r = j >> 4, c = j & 15;
            int row = tile * MT + r;
            if (row >= NN) row = 0;
            const __half* src = (half_ ? g_Al : g_Ah) + (size_t)row * EMB + c * 8;
            unsigned dst = dbase + (unsigned)half_ * ABYTES + (unsigned)(r * (BPAD * 2) + c * 16);
            cp16(dst, src);
        }
        asm volatile("cp.async.commit_group;" ::: "memory");
    };

    int tile = blockIdx.x;
    if (tile < NTILES) cpA(tile, 0);
    int nb = 1;
    for (; tile < NTILES; tile += GEMM_GRID_X) {
        int nxt = tile + GEMM_GRID_X;
        int cb = nb ^ 1;
        if (nxt < NTILES) {
            cpA(nxt, nb);
            asm volatile("cp.async.wait_group 1;" ::: "memory");
        } else {
            asm volatile("cp.async.wait_group 0;" ::: "memory");
        }
        __syncthreads();

        unsigned aAh = sbase + WBYTES + (unsigned)cb * 2u * ABYTES + lbase;
        unsigned aAl = aAh + ABYTES;

        float c[2][4][4];
        #pragma unroll
        for (int mb = 0; mb < 2; mb++)
            #pragma unroll
            for (int nt = 0; nt < 4; nt++)
                #pragma unroll
                for (int j = 0; j < 4; j++) c[mb][nt][j] = 0.f;

        #pragma unroll
        for (int ks = 0; ks < 8; ks++) {
            int k0 = ks * 16;
            unsigned ah[2][4], al[2][4];
            #pragma unroll
            for (int mb = 0; mb < 2; mb++) {
                ldm4(ah[mb], aAh + (unsigned)(mb * 16 * BPAD + k0) * 2);
                ldm4(al[mb], aAl + (unsigned)(mb * 16 * BPAD + k0) * 2);
            }
            #pragma unroll
            for (int nt16 = 0; nt16 < 2; nt16++) {
                #pragma unroll
                for (int mb = 0; mb < 2; mb++) {
                    mma_f16(c[mb][2 * nt16],     ah[mb], bhW[ks][nt16][0], bhW[ks][nt16][1]);
                    mma_f16(c[mb][2 * nt16 + 1], ah[mb], bhW[ks][nt16][2], bhW[ks][nt16][3]);
                }
                #pragma unroll
                for (int mb = 0; mb < 2; mb++) {
                    mma_f16(c[mb][2 * nt16],     al[mb], bhW[ks][nt16][0], bhW[ks][nt16][1]);
                    mma_f16(c[mb][2 * nt16 + 1], al[mb], bhW[ks][nt16][2], bhW[ks][nt16][3]);
                }
            }
        }

        int row0 = tile * MT;
        #pragma unroll
        for (int mb = 0; mb < 2; mb++) {
            int rA = row0 + mb * 16 + (lane >> 2);
            int rB = rA + 8;
            float sAs = 0.f, sAd = 0.f, sBs = 0.f, sBd = 0.f;
            #pragma unroll
            for (int nt = 0; nt < 4; nt++) {
                int col = nbase + nt * 8 + (lane & 3) * 2;
                sAs += c[mb][nt][0] * w0s[nt] + c[mb][nt][1] * w1s[nt];
                sAd += c[mb][nt][0] * w0d[nt] + c[mb][nt][1] * w1d[nt];
                sBs += c[mb][nt][2] * w0s[nt] + c[mb][nt][3] * w1s[nt];
                sBd += c[mb][nt][2] * w0d[nt] + c[mb][nt][3] * w1d[nt];
                if (rA < NN) *(__half2*)&Bout[(size_t)rA * EMB + col] =
                    __floats2half2_rn(c[mb][nt][0], c[mb][nt][1]);
                if (rB < NN) *(__half2*)&Bout[(size_t)rB * EMB + col] =
                    __floats2half2_rn(c[mb][nt][2], c[mb][nt][3]);
            }
            #pragma unroll
            for (int o = 1; o <= 2; o <<= 1) {
                sAs += __shfl_xor_sync(0xffffffffu, sAs, o);
                sAd += __shfl_xor_sync(0xffffffffu, sAd, o);
                sBs += __shfl_xor_sync(0xffffffffu, sBs, o);
                sBd += __shfl_xor_sync(0xffffffffu, sBd, o);
            }
            if ((lane & 3) == 0) {
                int rloc = mb * 16 + (lane >> 2);
                sredS[warp * 32 + rloc] = sAs;
                sredD[warp * 32 + rloc] = sAd;
                sredS[warp * 32 + rloc + 8] = sBs;
                sredD[warp * 32 + rloc + 8] = sBd;
            }
        }
        __syncthreads();
        if (tid < 32) {
            int row = row0 + tid;
            if (row < NN) {
                ssArr[row] = sredS[tid] + sredS[32 + tid] + sredS[64 + tid] + sredS[96 + tid];
                sdArr[row] = sredD[tid] + sredD[32 + tid] + sredD[64 + tid] + sredD[96 + tid];
            }
        }
        nb ^= 1;
    }
}

// ---------------- fused softmax aggregation; 1-ahead prefetch ---------------------
__global__ void aggregate_k(const int* __restrict__ node_type, const float* __restrict__ bias,
                            int convBase, const float* __restrict__ esc,
                            float* __restrict__ Out,
                            __half* __restrict__ outH, __half* __restrict__ outL) {
    int g = blockIdx.x * blockDim.x + threadIdx.x;
    int v = g >> 5, lane = threadIdx.x & 31;
    if (v >= NN) return;
    bool user = (node_type[v] == 0);
    const __half* H  = user ? g_B1h : g_B0h;
    const float* ss  = user ? g_ss1 : g_ss0;
    float sd         = user ? g_sd1[v] : g_sd0[v];
    int conv         = convBase + (user ? 1 : 0);
    const float* bi  = bias + (size_t)conv * EMB;

    int beg = g_rowptr[v], end = g_rowptr[v + 1];
    float4 acc = make_float4(0.f, 0.f, 0.f, 0.f);
    float denom = 0.f;
    if (beg < end) {
        int s = (int)__ldg(&g_src16[beg]);
        float ec = __ldg(&esc[beg]);
        for (int i = beg; i < end; i++) {
            int sn = 0; float ecn = 0.f;
            if (i + 1 < end) {
                sn = (int)__ldg(&g_src16[i + 1]);
                ecn = __ldg(&esc[i + 1]);
            }
            float a = ss[s] + sd + ec;
            a = (a > 0.f) ? a : 0.2f * a;
            float w = __expf(a);
            denom += w;
            uint2 hv = *(const uint2*)(H + (size_t)s * EMB + lane * 4);
            float2 f0 = __half22float2(*(__half2*)&hv.x);
            float2 f1 = __half22float2(*(__half2*)&hv.y);
            acc.x = fmaf(w, f0.x, acc.x);
            acc.y = fmaf(w, f0.y, acc.y);
            acc.z = fmaf(w, f1.x, acc.z);
            acc.w = fmaf(w, f1.y, acc.w);
            s = sn; ec = ecn;
        }
    }
    float inv = 1.f / (denom + 1e-16f);
    float4 bv = ((const float4*)bi)[lane];
    float4 o;
    o.x = fmaxf(fmaf(acc.x, inv, bv.x), 0.f);
    o.y = fmaxf(fmaf(acc.y, inv, bv.y), 0.f);
    o.z = fmaxf(fmaf(acc.z, inv, bv.z), 0.f);
    o.w = fmaxf(fmaf(acc.w, inv, bv.w), 0.f);
    if (outH) {
        __half h0 = __float2half_rn(o.x), h1 = __float2half_rn(o.y);
        __half h2 = __float2half_rn(o.z), h3 = __float2half_rn(o.w);
        uint2 Hh, Ll;
        *(__half2*)&Hh.x = __half2(h0, h1);
        *(__half2*)&Hh.y = __half2(h2, h3);
        *(__half2*)&Ll.x = __half2(__float2half_rn(o.x - __half2float(h0)),
                                   __float2half_rn(o.y - __half2float(h1)));
        *(__half2*)&Ll.y = __half2(__float2half_rn(o.z - __half2float(h2)),
                                   __float2half_rn(o.w - __half2float(h3)));
        *(uint2*)&outH[(size_t)v * EMB + lane * 4] = Hh;
        *(uint2*)&outL[(size_t)v * EMB + lane * 4] = Ll;
    } else {
        ((float4*)(Out + (size_t)v * EMB))[lane] = o;
    }
}

// ---------------- launch ----------------
extern "C" void kernel_launch(void* const* d_in, const int* in_sizes, int n_in,
                              void* d_out, int out_size) {
    const int*   node_ids  = (const int*)d_in[0];
    const int*   node_type = (const int*)d_in[1];
    const int*   edge_index= (const int*)d_in[2];
    const int*   edge_type = (const int*)d_in[3];
    const float* edge_attr = (const float*)d_in[4];
    const float* t         = (const float*)d_in[5];
    const float* emb       = (const float*)d_in[6];
    const float* timew     = (const float*)d_in[7];
    const float* timeb     = (const float*)d_in[8];
    const float* convW     = (const float*)d_in[9];
    const float* asrc      = (const float*)d_in[10];
    const float* adst      = (const float*)d_in[11];
    const float* eW        = (const float*)d_in[12];
    const float* aedge     = (const float*)d_in[13];
    const float* bias      = (const float*)d_in[14];
    float* out = (float*)d_out;

    __half* Ah_ptr = nullptr;
    cudaGetSymbolAddress((void**)&Ah_ptr, g_Ah);
    __half* Al_ptr = nullptr;
    cudaGetSymbolAddress((void**)&Al_ptr, g_Al);
    float* escA_ptr = nullptr;
    cudaGetSymbolAddress((void**)&escA_ptr, g_escA);
    float* escB_ptr = nullptr;
    cudaGetSymbolAddress((void**)&escB_ptr, g_escB);
    cudaFuncSetAttribute(gemm_mma_k, cudaFuncAttributeMaxDynamicSharedMemorySize, GEMM_SMEM);

    static cudaStream_t s2 = nullptr;
    static cudaEvent_t evFork = nullptr, evJoin = nullptr;
    if (!s2) {
        cudaStreamCreateWithFlags(&s2, cudaStreamNonBlocking);
        cudaEventCreateWithFlags(&evFork, cudaEventDisableTiming);
        cudaEventCreateWithFlags(&evJoin, cudaEventDisableTiming);
    }

    int nScanBlk = (NN + 1023) / 1024;  // 49
    int preGrid = (PRE_W64 + PRE_W + NN + 255) / 256;
    dim3 ggrid(GEMM_GRID_X, 1, 2);

    // 0: root
    precompute_k<<<preGrid, 256>>>(eW, aedge, convW);
    cudaEventRecord(evFork, 0);
    cudaStreamWaitEvent(s2, evFork, 0);

    // 1: hist (side arm start)
    hist_k<<<(NE + 255) / 256, 256, 0, s2>>>(edge_index, edge_type, node_type);
    // 2-3: main arm — gemm1 at launch index 3 for ncu
    splitA_emb_k<<<(NN * 32 + 255) / 256, 256>>>(node_ids, emb);
    gemm_mma_k<<<ggrid, 128, GEMM_SMEM>>>(asrc, adst, 0);
    // 4-5: rest of side arm
    scanF_k<<<nScanBlk, 1024, 0, s2>>>();
    scatter_k<<<(NE + 255) / 256, 256, 0, s2>>>(edge_index, edge_type, node_type,
                                                edge_attr, t, timew, timeb);
    cudaEventRecord(evJoin, s2);

    // join, serial tail
    cudaStreamWaitEvent(0, evJoin, 0);
    aggregate_k<<<(NN * 32 + 255) / 256, 256>>>(node_type, bias, 0, escA_ptr,
                                                nullptr, Ah_ptr, Al_ptr);
    gemm_mma_k<<<ggrid, 128, GEMM_SMEM>>>(asrc, adst, 2);
    aggregate_k<<<(NN * 32 + 255) / 256, 256>>>(node_type, bias, 2, escB_ptr,
                                                out, nullptr, nullptr);
}

// round 15
// speedup vs baseline: 1.0324x; 1.0324x over previous
#include <cuda_runtime.h>
#include <cuda_fp16.h>

#define NN 50000
#define NE 600000
#define EMB 128
#define TDIM 32
#define RAW 32

// ---------------- scratch (static device globals; no allocation) ----------------
static __device__ __align__(16) __half g_Ah[NN * EMB];   // A hi (fp16)
static __device__ __align__(16) __half g_Al[NN * EMB];   // A residual (fp16)
static __device__ __align__(16) __half g_B0h[NN * EMB];  // h (conv even), fp16
static __device__ __align__(16) __half g_B1h[NN * EMB];  // h (conv odd), fp16
static __device__ float g_w64[4 * 64];                   // eW @ a_edge per conv
static __device__ __align__(16) __half g_Wt16[4 * EMB * EMB];  // W fp16 TRANSPOSED [conv][n][k]
static __device__ int   g_deg[NN];
static __device__ int   g_rowptr[NN + 1];
static __device__ int   g_cur[NN];
static __device__ int   g_bsum[64];
static __device__ int   g_boff[64];
static __device__ int   g_scanCnt;
static __device__ volatile int g_scanFlag;
static __device__ unsigned short g_src16[NE];
static __device__ float g_escA[NE];
static __device__ float g_escB[NE];
// per (conv-parity, N-half) partial attention dots: z = parity*2 + half
static __device__ float g_ssH[4][NN];
static __device__ float g_sdH[4][NN];

// ---------------- PTX helpers ----------------
__device__ __forceinline__ unsigned smem_u32(const void* p) {
    unsigned r;
    asm("{ .reg .u64 t; cvta.to.shared.u64 t, %1; cvt.u32.u64 %0, t; }" : "=r"(r) : "l"(p));
    return r;
}
__device__ __forceinline__ void ldm4(unsigned* r, unsigned addr) {
    asm volatile("ldmatrix.sync.aligned.m8n8.x4.shared.b16 {%0,%1,%2,%3}, [%4];"
                 : "=r"(r[0]), "=r"(r[1]), "=r"(r[2]), "=r"(r[3]) : "r"(addr));
}
__device__ __forceinline__ void mma_f16(float* c, const unsigned* a, unsigned b0, unsigned b1) {
    asm volatile("mma.sync.aligned.m16n8k16.row.col.f32.f16.f16.f32 "
                 "{%0,%1,%2,%3}, {%4,%5,%6,%7}, {%8,%9}, {%0,%1,%2,%3};"
                 : "+f"(c[0]), "+f"(c[1]), "+f"(c[2]), "+f"(c[3])
                 : "r"(a[0]), "r"(a[1]), "r"(a[2]), "r"(a[3]), "r"(b0), "r"(b1));
}
__device__ __forceinline__ void cp16(unsigned dst, const void* src) {
    asm volatile("cp.async.cg.shared.global [%0], [%1], 16;" :: "r"(dst), "l"(src));
}

// ---------------- root kernel: w64 + fp16 W^T + zero deg/cur/scan state ----------
#define PRE_W64 256
#define PRE_W (4 * EMB * EMB)
__global__ void precompute_k(const float* __restrict__ eW, const float* __restrict__ aedge,
                             const float* __restrict__ W) {
    int idx = blockIdx.x * blockDim.x + threadIdx.x;
    if (idx == 0) { g_scanCnt = 0; g_scanFlag = 0; }
    if (idx < PRE_W64) {
        int c = idx >> 6, j = idx & 63;
        const float* ew = eW + (c * 64 + j) * EMB;
        const float* ae = aedge + c * EMB;
        float s = 0.f;
        #pragma unroll 8
        for (int f = 0; f < EMB; f++) s = fmaf(ew[f], ae[f], s);
        g_w64[idx] = s;
    } else if (idx < PRE_W64 + PRE_W) {
        int i = idx - PRE_W64;
        int c = i >> 14, rem = i & 16383;
        int n = rem >> 7, k = rem & 127;
        g_Wt16[i] = __float2half_rn(W[c * 16384 + k * 128 + n]);   // transpose
    } else {
        int i = idx - PRE_W64 - PRE_W;
        if (i < NN) { g_deg[i] = 0; g_cur[i] = 0; }
    }
}

// ---------------- A split: layer 1 (gather emb + split fp16 hi/lo) ----------------
__global__ void splitA_emb_k(const int* __restrict__ ids, const float* __restrict__ emb) {
    int i = blockIdx.x * blockDim.x + threadIdx.x;
    if (i >= NN * 32) return;
    int v = i >> 5, c = i & 31;
    float4 x = ((const float4*)emb)[(size_t)__ldg(&ids[v]) * 32 + c];
    __half h0 = __float2half_rn(x.x), h1 = __float2half_rn(x.y);
    __half h2 = __float2half_rn(x.z), h3 = __float2half_rn(x.w);
    uint2 H, L;
    *(__half2*)&H.x = __half2(h0, h1);
    *(__half2*)&H.y = __half2(h2, h3);
    *(__half2*)&L.x = __half2(__float2half_rn(x.x - __half2float(h0)),
                              __float2half_rn(x.y - __half2float(h1)));
    *(__half2*)&L.y = __half2(__float2half_rn(x.z - __half2float(h2)),
                              __float2half_rn(x.w - __half2float(h3)));
    *(uint2*)&g_Ah[(size_t)v * EMB + c * 4] = H;
    *(uint2*)&g_Al[(size_t)v * EMB + c * 4] = L;
}

// ---------------- CSR build (only edges whose type matches dst's node type) ------
__global__ void hist_k(const int* __restrict__ ei, const int* __restrict__ etype,
                       const int* __restrict__ ntype) {
    int e = blockIdx.x * blockDim.x + threadIdx.x;
    if (e >= NE) return;
    int dst = ei[NE + e];
    int req = (__ldg(&ntype[dst]) == 0) ? 1 : 0;
    if (etype[e] == req) atomicAdd(&g_deg[dst], 1);
}

// fused scan (49 co-resident blocks)
__global__ void scanF_k() {
    __shared__ int ws[32];
    __shared__ int s_last;
    int tid = threadIdx.x, lane = tid & 31, wid = tid >> 5;
    int i = blockIdx.x * 1024 + tid;
    int v = (i < NN) ? g_deg[i] : 0;
    int x = v;
    #pragma unroll
    for (int o = 1; o < 32; o <<= 1) {
        int y = __shfl_up_sync(0xffffffffu, x, o);
        if (lane >= o) x += y;
    }
    if (lane == 31) ws[wid] = x;
    __syncthreads();
    if (wid == 0) {
        int s = ws[lane];
        #pragma unroll
        for (int o = 1; o < 32; o <<= 1) {
            int y = __shfl_up_sync(0xffffffffu, s, o);
            if (lane >= o) s += y;
        }
        ws[lane] = s;
    }
    __syncthreads();
    int incl = x + (wid > 0 ? ws[wid - 1] : 0);
    int myexc = incl - v;
    if (tid == 1023) g_bsum[blockIdx.x] = incl;
    __threadfence();
    if (tid == 0) s_last = (atomicAdd(&g_scanCnt, 1) == (int)gridDim.x - 1);
    __syncthreads();
    if (s_last) {
        int bv = 0, bx = 0;
        if (tid < 64) {
            bv = (tid < (int)gridDim.x) ? g_bsum[tid] : 0;
            bx = bv;
            #pragma unroll
            for (int o = 1; o < 32; o <<= 1) {
                int y = __shfl_up_sync(0xffffffffu, bx, o);
                if (lane >= o) bx += y;
            }
            if (lane == 31) ws[wid] = bx;
        }
        __syncthreads();
        if (tid < 64) {
            int incl2 = bx + (tid >= 32 ? ws[0] : 0);
            g_boff[tid] = incl2 - bv;
            if (tid == 63) g_rowptr[NN] = incl2;
        }
        __threadfence();
        __syncthreads();
        if (tid == 0) g_scanFlag = 1;
    }
    if (tid == 0) {
        while (g_scanFlag == 0) __nanosleep(64);
    }
    __syncthreads();
    __threadfence();
    if (i < NN) g_rowptr[i] = myexc + g_boff[blockIdx.x];
}

__global__ void scatter_k(const int* __restrict__ ei, const int* __restrict__ etype,
                          const int* __restrict__ ntype,
                          const float* __restrict__ eattr, const float* __restrict__ t,
                          const float* __restrict__ timew, const float* __restrict__ timeb) {
    int e = blockIdx.x * blockDim.x + threadIdx.x;
    if (e >= NE) return;
    int dst = ei[NE + e];
    int user = (__ldg(&ntype[dst]) == 0) ? 1 : 0;
    if (etype[e] != user) return;
    int src = ei[e];
    int pos = g_rowptr[dst] + atomicAdd(&g_cur[dst], 1);
    g_src16[pos] = (unsigned short)src;

    const float* w1 = g_w64 + user * 64;
    const float* w2 = g_w64 + (2 + user) * 64;
    float tv = t[e];
    float e1 = 0.f, e2 = 0.f;
    #pragma unroll 8
    for (int j = 0; j < TDIM; j++) {
        float te = __cosf(fmaf(tv, timew[j], timeb[j]));
        e1 = fmaf(te, w1[j], e1);
        e2 = fmaf(te, w2[j], e2);
    }
    const float4* ar = (const float4*)(eattr + (size_t)e * RAW);
    #pragma unroll
    for (int q = 0; q < 8; q++) {
        float4 av = ar[q];
        int j = 32 + q * 4;
        e1 = fmaf(av.x, w1[j], e1);     e1 = fmaf(av.y, w1[j + 1], e1);
        e1 = fmaf(av.z, w1[j + 2], e1); e1 = fmaf(av.w, w1[j + 3], e1);
        e2 = fmaf(av.x, w2[j], e2);     e2 = fmaf(av.y, w2[j + 1], e2);
        e2 = fmaf(av.z, w2[j + 2], e2); e2 = fmaf(av.w, w2[j + 3], e2);
    }
    g_escA[pos] = e1;
    g_escB[pos] = e2;
}

// ---------------- persistent fp16 2-term GEMM, 4 CTAs/SM ---------------------------
// grid (148,1,4): z = (conv, N-half). CTA: 128 threads, tile M=32 x N=64.
// Warp w owns 16 cols. W fragments loaded DIRECTLY from transposed global Wt
// (32 regs/thread, no W smem, no ldmatrix.trans). Smem = A double buffer only.
#define BPAD 136
#define MT 32
#define NTILES ((NN + MT - 1) / MT)    // 1563
#define GEMM_GRID_X 148                // x4 z -> 592 CTAs -> 4/SM
#define ABYTES (MT * BPAD * 2)         // 8704
#define SMEM_RED_OFF (4 * ABYTES)
#define GEMM_SMEM (4 * ABYTES + 1280)

__global__ void __launch_bounds__(128, 4) gemm_mma_k(const float* __restrict__ asrc,
                                                     const float* __restrict__ adst,
                                                     int convBase) {
    extern __shared__ __align__(16) char smraw[];
    float* sredS = (float*)(smraw + SMEM_RED_OFF);        // [4][32]
    float* sredD = sredS + 128;                           // [4][32]
    unsigned sbase = smem_u32(smraw);

    int zz = blockIdx.z;
    int conv = convBase + (zz >> 1);
    int halfN = (zz & 1) * 64;
    __half* Bout = (zz >> 1) ? g_B1h : g_B0h;
    float* ssArr = g_ssH[zz];
    float* sdArr = g_sdH[zz];
    int tid = threadIdx.x;
    int lane = tid & 31, warp = tid >> 5;
    int ncol0 = halfN + warp * 16;                        // warp's global col base

    // W fragments direct from transposed global: b0 @ Wt[n][k0+(lane&3)*2], b1 @ +8
    const __half* Wt = g_Wt16 + (size_t)conv * EMB * EMB;
    unsigned bw[8][2][2];
    {
        int nf = ncol0 + (lane >> 2);
        int kf = (lane & 3) * 2;
        #pragma unroll
        for (int ks = 0; ks < 8; ks++)
            #pragma unroll
            for (int nt = 0; nt < 2; nt++) {
                const __half* p = Wt + (size_t)(nf + nt * 8) * EMB + ks * 16 + kf;
                bw[ks][nt][0] = *(const unsigned*)p;
                bw[ks][nt][1] = *(const unsigned*)(p + 8);
            }
    }

    const float* aS = asrc + (size_t)conv * EMB;
    const float* aD = adst + (size_t)conv * EMB;
    float w0s[2], w1s[2], w0d[2], w1d[2];
    #pragma unroll
    for (int nt = 0; nt < 2; nt++) {
        int col = ncol0 + nt * 8 + (lane & 3) * 2;
        w0s[nt] = aS[col]; w1s[nt] = aS[col + 1];
        w0d[nt] = aD[col]; w1d[nt] = aD[col + 1];
    }

    unsigned lbase = ((unsigned)((lane & 15) * BPAD + 8 * (lane >> 4))) * 2;

    auto cpA = [&](int tile, int b) {
        unsigned dbase = sbase + (unsigned)b * 2u * ABYTES;
        #pragma unroll
        for (int ii = 0; ii < 8; ii++) {
            int i = tid + ii * 128;
            int half_ = i >> 9;
            int j = i & 511;
            int r = j >> 4, c = j & 15;
            int row = tile * MT + r;
            if (row >= NN) row = 0;
            const __half* src = (half_ ? g_Al : g_Ah) + (size_t)row * EMB + c * 8;
            unsigned dst = dbase + (unsigned)half_ * ABYTES + (unsigned)(r * (BPAD * 2) + c * 16);
            cp16(dst, src);
        }
        asm volatile("cp.async.commit_group;" ::: "memory");
    };

    int tile = blockIdx.x;
    if (tile < NTILES) cpA(tile, 0);
    int nb = 1;
    for (; tile < NTILES; tile += GEMM_GRID_X) {
        int nxt = tile + GEMM_GRID_X;
        int cb = nb ^ 1;
        if (nxt < NTILES) {
            cpA(nxt, nb);
            asm volatile("cp.async.wait_group 1;" ::: "memory");
        } else {
            asm volatile("cp.async.wait_group 0;" ::: "memory");
        }
        __syncthreads();

        unsigned aAh = sbase + (unsigned)cb * 2u * ABYTES + lbase;
        unsigned aAl = aAh + ABYTES;

        float c[2][2][4];
        #pragma unroll
        for (int mb = 0; mb < 2; mb++)
            #pragma unroll
            for (int nt = 0; nt < 2; nt++)
                #pragma unroll
                for (int j = 0; j < 4; j++) c[mb][nt][j] = 0.f;

        #pragma unroll
        for (int ks = 0; ks < 8; ks++) {
            int k0 = ks * 16;
            unsigned ah[2][4], al[2][4];
            #pragma unroll
            for (int mb = 0; mb < 2; mb++) {
                ldm4(ah[mb], aAh + (unsigned)(mb * 16 * BPAD + k0) * 2);
                ldm4(al[mb], aAl + (unsigned)(mb * 16 * BPAD + k0) * 2);
            }
            #pragma unroll
            for (int nt = 0; nt < 2; nt++) {
                #pragma unroll
                for (int mb = 0; mb < 2; mb++)
                    mma_f16(c[mb][nt], ah[mb], bw[ks][nt][0], bw[ks][nt][1]);
                #pragma unroll
                for (int mb = 0; mb < 2; mb++)
                    mma_f16(c[mb][nt], al[mb], bw[ks][nt][0], bw[ks][nt][1]);
            }
        }

        int row0 = tile * MT;
        #pragma unroll
        for (int mb = 0; mb < 2; mb++) {
            int rA = row0 + mb * 16 + (lane >> 2);
            int rB = rA + 8;
            float sAs = 0.f, sAd = 0.f, sBs = 0.f, sBd = 0.f;
            #pragma unroll
            for (int nt = 0; nt < 2; nt++) {
                int col = ncol0 + nt * 8 + (lane & 3) * 2;
                sAs += c[mb][nt][0] * w0s[nt] + c[mb][nt][1] * w1s[nt];
                sAd += c[mb][nt][0] * w0d[nt] + c[mb][nt][1] * w1d[nt];
                sBs += c[mb][nt][2] * w0s[nt] + c[mb][nt][3] * w1s[nt];
                sBd += c[mb][nt][2] * w0d[nt] + c[mb][nt][3] * w1d[nt];
                if (rA < NN) *(__half2*)&Bout[(size_t)rA * EMB + col] =
                    __floats2half2_rn(c[mb][nt][0], c[mb][nt][1]);
                if (rB < NN) *(__half2*)&Bout[(size_t)rB * EMB + col] =
                    __floats2half2_rn(c[mb][nt][2], c[mb][nt][3]);
            }
            #pragma unroll
            for (int o = 1; o <= 2; o <<= 1) {
                sAs += __shfl_xor_sync(0xffffffffu, sAs, o);
                sAd += __shfl_xor_sync(0xffffffffu, sAd, o);
                sBs += __shfl_xor_sync(0xffffffffu, sBs, o);
                sBd += __shfl_xor_sync(0xffffffffu, sBd, o);
            }
            if ((lane & 3) == 0) {
                int rloc = mb * 16 + (lane >> 2);
                sredS[warp * 32 + rloc] = sAs;
                sredD[warp * 32 + rloc] = sAd;
                sredS[warp * 32 + rloc + 8] = sBs;
                sredD[warp * 32 + rloc + 8] = sBd;
            }
        }
        __syncthreads();
        if (tid < 32) {
            int row = row0 + tid;
            if (row < NN) {
                ssArr[row] = sredS[tid] + sredS[32 + tid] + sredS[64 + tid] + sredS[96 + tid];
                sdArr[row] = sredD[tid] + sredD[32 + tid] + sredD[64 + tid] + sredD[96 + tid];
            }
        }
        nb ^= 1;
    }
}

// ---------------- fused softmax aggregation; partial-score sum; prefetch ----------
__global__ void aggregate_k(const int* __restrict__ node_type, const float* __restrict__ bias,
                            int convBase, const float* __restrict__ esc,
                            float* __restrict__ Out,
                            __half* __restrict__ outH, __half* __restrict__ outL) {
    int g = blockIdx.x * blockDim.x + threadIdx.x;
    int v = g >> 5, lane = threadIdx.x & 31;
    if (v >= NN) return;
    bool user = (node_type[v] == 0);
    const __half* H   = user ? g_B1h : g_B0h;
    int p             = user ? 2 : 0;                 // z base = parity*2
    const float* ss0  = g_ssH[p];
    const float* ss1  = g_ssH[p + 1];
    float sd          = g_sdH[p][v] + g_sdH[p + 1][v];
    int conv          = convBase + (user ? 1 : 0);
    const float* bi   = bias + (size_t)conv * EMB;

    int beg = g_rowptr[v], end = g_rowptr[v + 1];
    float4 acc = make_float4(0.f, 0.f, 0.f, 0.f);
    float denom = 0.f;
    if (beg < end) {
        int s = (int)__ldg(&g_src16[beg]);
        float ec = __ldg(&esc[beg]);
        for (int i = beg; i < end; i++) {
            int sn = 0; float ecn = 0.f;
            if (i + 1 < end) {
                sn = (int)__ldg(&g_src16[i + 1]);
                ecn = __ldg(&esc[i + 1]);
            }
            float a = ss0[s] + ss1[s] + sd + ec;
            a = (a > 0.f) ? a : 0.2f * a;
            float w = __expf(a);
            denom += w;
            uint2 hv = *(const uint2*)(H + (size_t)s * EMB + lane * 4);
            float2 f0 = __half22float2(*(__half2*)&hv.x);
            float2 f1 = __half22float2(*(__half2*)&hv.y);
            acc.x = fmaf(w, f0.x, acc.x);
            acc.y = fmaf(w, f0.y, acc.y);
            acc.z = fmaf(w, f1.x, acc.z);
            acc.w = fmaf(w, f1.y, acc.w);
            s = sn; ec = ecn;
        }
    }
    float inv = 1.f / (denom + 1e-16f);
    float4 bv = ((const float4*)bi)[lane];
    float4 o;
    o.x = fmaxf(fmaf(acc.x, inv, bv.x), 0.f);
    o.y = fmaxf(fmaf(acc.y, inv, bv.y), 0.f);
    o.z = fmaxf(fmaf(acc.z, inv, bv.z), 0.f);
    o.w = fmaxf(fmaf(acc.w, inv, bv.w), 0.f);
    if (outH) {
        __half h0 = __float2half_rn(o.x), h1 = __float2half_rn(o.y);
        __half h2 = __float2half_rn(o.z), h3 = __float2half_rn(o.w);
        uint2 Hh, Ll;
        *(__half2*)&Hh.x = __half2(h0, h1);
        *(__half2*)&Hh.y = __half2(h2, h3);
        *(__half2*)&Ll.x = __half2(__float2half_rn(o.x - __half2float(h0)),
                                   __float2half_rn(o.y - __half2float(h1)));
        *(__half2*)&Ll.y = __half2(__float2half_rn(o.z - __half2float(h2)),
                                   __float2half_rn(o.w - __half2float(h3)));
        *(uint2*)&outH[(size_t)v * EMB + lane * 4] = Hh;
        *(uint2*)&outL[(size_t)v * EMB + lane * 4] = Ll;
    } else {
        ((float4*)(Out + (size_t)v * EMB))[lane] = o;
    }
}

// ---------------- launch ----------------
extern "C" void kernel_launch(void* const* d_in, const int* in_sizes, int n_in,
                              void* d_out, int out_size) {
    const int*   node_ids  = (const int*)d_in[0];
    const int*   node_type = (const int*)d_in[1];
    const int*   edge_index= (const int*)d_in[2];
    const int*   edge_type = (const int*)d_in[3];
    const float* edge_attr = (const float*)d_in[4];
    const float* t         = (const float*)d_in[5];
    const float* emb       = (const float*)d_in[6];
    const float* timew     = (const float*)d_in[7];
    const float* timeb     = (const float*)d_in[8];
    const float* convW     = (const float*)d_in[9];
    const float* asrc      = (const float*)d_in[10];
    const float* adst      = (const float*)d_in[11];
    const float* eW        = (const float*)d_in[12];
    const float* aedge     = (const float*)d_in[13];
    const float* bias      = (const float*)d_in[14];
    float* out = (float*)d_out;

    __half* Ah_ptr = nullptr;
    cudaGetSymbolAddress((void**)&Ah_ptr, g_Ah);
    __half* Al_ptr = nullptr;
    cudaGetSymbolAddress((void**)&Al_ptr, g_Al);
    float* escA_ptr = nullptr;
    cudaGetSymbolAddress((void**)&escA_ptr, g_escA);
    float* escB_ptr = nullptr;
    cudaGetSymbolAddress((void**)&escB_ptr, g_escB);
    cudaFuncSetAttribute(gemm_mma_k, cudaFuncAttributeMaxDynamicSharedMemorySize, GEMM_SMEM);

    static cudaStream_t s2 = nullptr;
    static cudaEvent_t evFork = nullptr, evJoin = nullptr;
    if (!s2) {
        cudaStreamCreateWithFlags(&s2, cudaStreamNonBlocking);
        cudaEventCreateWithFlags(&evFork, cudaEventDisableTiming);
        cudaEventCreateWithFlags(&evJoin, cudaEventDisableTiming);
    }

    int nScanBlk = (NN + 1023) / 1024;  // 49
    int preGrid = (PRE_W64 + PRE_W + NN + 255) / 256;
    dim3 ggrid(GEMM_GRID_X, 1, 4);

    // 0: root
    precompute_k<<<preGrid, 256>>>(eW, aedge, convW);
    cudaEventRecord(evFork, 0);
    cudaStreamWaitEvent(s2, evFork, 0);

    // 1: hist (side arm start)
    hist_k<<<(NE + 255) / 256, 256, 0, s2>>>(edge_index, edge_type, node_type);
    // 2-3: main arm — gemm1 at launch index 3 for ncu
    splitA_emb_k<<<(NN * 32 + 255) / 256, 256>>>(node_ids, emb);
    gemm_mma_k<<<ggrid, 128, GEMM_SMEM>>>(asrc, adst, 0);
    // 4-5: rest of side arm
    scanF_k<<<nScanBlk, 1024, 0, s2>>>();
    scatter_k<<<(NE + 255) / 256, 256, 0, s2>>>(edge_index, edge_type, node_type,
                                                edge_attr, t, timew, timeb);
    cudaEventRecord(evJoin, s2);

    // join, serial tail
    cudaStreamWaitEvent(0, evJoin, 0);
    aggregate_k<<<(NN * 32 + 255) / 256, 256>>>(node_type, bias, 0, escA_ptr,
                                                nullptr, Ah_ptr, Al_ptr);
    gemm_mma_k<<<ggrid, 128, GEMM_SMEM>>>(asrc, adst, 2);
    aggregate_k<<<(NN * 32 + 255) / 256, 256>>>(node_type, bias, 2, escB_ptr,
                                                out, nullptr, nullptr);
}

// round 16
// speedup vs baseline: 1.1420x; 1.1061x over previous
#include <cuda_runtime.h>
#include <cuda_fp16.h>

#define NN 50000
#define NE 600000
#define EMB 128
#define TDIM 32
#define RAW 32

// ---------------- scratch (static device globals; no allocation) ----------------
static __device__ __align__(16) __half g_Ah[NN * EMB];   // A (fp16)
static __device__ __align__(16) __half g_B0h[NN * EMB];  // h (conv even), fp16
static __device__ __align__(16) __half g_B1h[NN * EMB];  // h (conv odd), fp16
static __device__ float g_w64[4 * 64];                   // eW @ a_edge per conv
static __device__ __align__(16) __half g_Wt16[4 * EMB * EMB];  // W fp16 TRANSPOSED [conv][n][k]
static __device__ int   g_deg[NN];
static __device__ int   g_rowptr[NN + 1];
static __device__ int   g_cur[NN];
static __device__ int   g_bsum[64];
static __device__ int   g_boff[64];
static __device__ int   g_scanCnt;
static __device__ volatile int g_scanFlag;
static __device__ unsigned short g_src16[NE];
static __device__ float g_escA[NE];
static __device__ float g_escB[NE];
// per (conv-parity, N-half) partial attention dots: z = parity*2 + half
static __device__ float g_ssH[4][NN];
static __device__ float g_sdH[4][NN];

// ---------------- PTX helpers ----------------
__device__ __forceinline__ unsigned smem_u32(const void* p) {
    unsigned r;
    asm("{ .reg .u64 t; cvta.to.shared.u64 t, %1; cvt.u32.u64 %0, t; }" : "=r"(r) : "l"(p));
    return r;
}
__device__ __forceinline__ void ldm4(unsigned* r, unsigned addr) {
    asm volatile("ldmatrix.sync.aligned.m8n8.x4.shared.b16 {%0,%1,%2,%3}, [%4];"
                 : "=r"(r[0]), "=r"(r[1]), "=r"(r[2]), "=r"(r[3]) : "r"(addr));
}
__device__ __forceinline__ void mma_f16(float* c, const unsigned* a, unsigned b0, unsigned b1) {
    asm volatile("mma.sync.aligned.m16n8k16.row.col.f32.f16.f16.f32 "
                 "{%0,%1,%2,%3}, {%4,%5,%6,%7}, {%8,%9}, {%0,%1,%2,%3};"
                 : "+f"(c[0]), "+f"(c[1]), "+f"(c[2]), "+f"(c[3])
                 : "r"(a[0]), "r"(a[1]), "r"(a[2]), "r"(a[3]), "r"(b0), "r"(b1));
}
__device__ __forceinline__ void cp16(unsigned dst, const void* src) {
    asm volatile("cp.async.cg.shared.global [%0], [%1], 16;" :: "r"(dst), "l"(src));
}

// ---------------- root kernel: w64 + fp16 W^T + zero deg/cur/scan state ----------
#define PRE_W64 256
#define PRE_W (4 * EMB * EMB)
__global__ void precompute_k(const float* __restrict__ eW, const float* __restrict__ aedge,
                             const float* __restrict__ W) {
    int idx = blockIdx.x * blockDim.x + threadIdx.x;
    if (idx == 0) { g_scanCnt = 0; g_scanFlag = 0; }
    if (idx < PRE_W64) {
        int c = idx >> 6, j = idx & 63;
        const float* ew = eW + (c * 64 + j) * EMB;
        const float* ae = aedge + c * EMB;
        float s = 0.f;
        #pragma unroll 8
        for (int f = 0; f < EMB; f++) s = fmaf(ew[f], ae[f], s);
        g_w64[idx] = s;
    } else if (idx < PRE_W64 + PRE_W) {
        int i = idx - PRE_W64;
        int c = i >> 14, rem = i & 16383;
        int n = rem >> 7, k = rem & 127;
        g_Wt16[i] = __float2half_rn(W[c * 16384 + k * 128 + n]);   // transpose
    } else {
        int i = idx - PRE_W64 - PRE_W;
        if (i < NN) { g_deg[i] = 0; g_cur[i] = 0; }
    }
}

// ---------------- A: layer 1 (gather emb -> fp16) ---------------------------------
__global__ void splitA_emb_k(const int* __restrict__ ids, const float* __restrict__ emb) {
    int i = blockIdx.x * blockDim.x + threadIdx.x;
    if (i >= NN * 32) return;
    int v = i >> 5, c = i & 31;
    float4 x = ((const float4*)emb)[(size_t)__ldg(&ids[v]) * 32 + c];
    uint2 H;
    *(__half2*)&H.x = __floats2half2_rn(x.x, x.y);
    *(__half2*)&H.y = __floats2half2_rn(x.z, x.w);
    *(uint2*)&g_Ah[(size_t)v * EMB + c * 4] = H;
}

// ---------------- CSR build (only edges whose type matches dst's node type) ------
__global__ void hist_k(const int* __restrict__ ei, const int* __restrict__ etype,
                       const int* __restrict__ ntype) {
    int e = blockIdx.x * blockDim.x + threadIdx.x;
    if (e >= NE) return;
    int dst = ei[NE + e];
    int req = (__ldg(&ntype[dst]) == 0) ? 1 : 0;
    if (etype[e] == req) atomicAdd(&g_deg[dst], 1);
}

// fused scan (49 co-resident blocks)
__global__ void scanF_k() {
    __shared__ int ws[32];
    __shared__ int s_last;
    int tid = threadIdx.x, lane = tid & 31, wid = tid >> 5;
    int i = blockIdx.x * 1024 + tid;
    int v = (i < NN) ? g_deg[i] : 0;
    int x = v;
    #pragma unroll
    for (int o = 1; o < 32; o <<= 1) {
        int y = __shfl_up_sync(0xffffffffu, x, o);
        if (lane >= o) x += y;
    }
    if (lane == 31) ws[wid] = x;
    __syncthreads();
    if (wid == 0) {
        int s = ws[lane];
        #pragma unroll
        for (int o = 1; o < 32; o <<= 1) {
            int y = __shfl_up_sync(0xffffffffu, s, o);
            if (lane >= o) s += y;
        }
        ws[lane] = s;
    }
    __syncthreads();
    int incl = x + (wid > 0 ? ws[wid - 1] : 0);
    int myexc = incl - v;
    if (tid == 1023) g_bsum[blockIdx.x] = incl;
    __threadfence();
    if (tid == 0) s_last = (atomicAdd(&g_scanCnt, 1) == (int)gridDim.x - 1);
    __syncthreads();
    if (s_last) {
        int bv = 0, bx = 0;
        if (tid < 64) {
            bv = (tid < (int)gridDim.x) ? g_bsum[tid] : 0;
            bx = bv;
            #pragma unroll
            for (int o = 1; o < 32; o <<= 1) {
                int y = __shfl_up_sync(0xffffffffu, bx, o);
                if (lane >= o) bx += y;
            }
            if (lane == 31) ws[wid] = bx;
        }
        __syncthreads();
        if (tid < 64) {
            int incl2 = bx + (tid >= 32 ? ws[0] : 0);
            g_boff[tid] = incl2 - bv;
            if (tid == 63) g_rowptr[NN] = incl2;
        }
        __threadfence();
        __syncthreads();
        if (tid == 0) g_scanFlag = 1;
    }
    if (tid == 0) {
        while (g_scanFlag == 0) __nanosleep(64);
    }
    __syncthreads();
    __threadfence();
    if (i < NN) g_rowptr[i] = myexc + g_boff[blockIdx.x];
}

__global__ void scatter_k(const int* __restrict__ ei, const int* __restrict__ etype,
                          const int* __restrict__ ntype,
                          const float* __restrict__ eattr, const float* __restrict__ t,
                          const float* __restrict__ timew, const float* __restrict__ timeb) {
    int e = blockIdx.x * blockDim.x + threadIdx.x;
    if (e >= NE) return;
    int dst = ei[NE + e];
    int user = (__ldg(&ntype[dst]) == 0) ? 1 : 0;
    if (etype[e] != user) return;
    int src = ei[e];
    int pos = g_rowptr[dst] + atomicAdd(&g_cur[dst], 1);
    g_src16[pos] = (unsigned short)src;

    const float* w1 = g_w64 + user * 64;
    const float* w2 = g_w64 + (2 + user) * 64;
    float tv = t[e];
    float e1 = 0.f, e2 = 0.f;
    #pragma unroll 8
    for (int j = 0; j < TDIM; j++) {
        float te = __cosf(fmaf(tv, timew[j], timeb[j]));
        e1 = fmaf(te, w1[j], e1);
        e2 = fmaf(te, w2[j], e2);
    }
    const float4* ar = (const float4*)(eattr + (size_t)e * RAW);
    #pragma unroll
    for (int q = 0; q < 8; q++) {
        float4 av = ar[q];
        int j = 32 + q * 4;
        e1 = fmaf(av.x, w1[j], e1);     e1 = fmaf(av.y, w1[j + 1], e1);
        e1 = fmaf(av.z, w1[j + 2], e1); e1 = fmaf(av.w, w1[j + 3], e1);
        e2 = fmaf(av.x, w2[j], e2);     e2 = fmaf(av.y, w2[j + 1], e2);
        e2 = fmaf(av.z, w2[j + 2], e2); e2 = fmaf(av.w, w2[j + 3], e2);
    }
    g_escA[pos] = e1;
    g_escB[pos] = e2;
}

// ---------------- persistent fp16 single-term GEMM, 5 CTAs/SM ---------------------
// grid (185,1,4): z = (conv, N-half). CTA: 128 threads, tile M=32 x N=64.
// W fragments direct from transposed global (16 u32 regs). A single fp16 buffer,
// cp.async double-buffered. No residual term (A quantized to fp16; ~2-4e-4 rel err).
#define BPAD 136
#define MT 32
#define NTILES ((NN + MT - 1) / MT)    // 1563
#define GEMM_GRID_X 185                // x4 z -> 740 CTAs -> 5/SM
#define ABYTES (MT * BPAD * 2)         // 8704
#define SMEM_RED_OFF (2 * ABYTES)
#define GEMM_SMEM (2 * ABYTES + 1280)

__global__ void __launch_bounds__(128, 5) gemm_mma_k(const float* __restrict__ asrc,
                                                     const float* __restrict__ adst,
                                                     int convBase) {
    extern __shared__ __align__(16) char smraw[];
    float* sredS = (float*)(smraw + SMEM_RED_OFF);        // [4][32]
    float* sredD = sredS + 128;                           // [4][32]
    unsigned sbase = smem_u32(smraw);

    int zz = blockIdx.z;
    int conv = convBase + (zz >> 1);
    int halfN = (zz & 1) * 64;
    __half* Bout = (zz >> 1) ? g_B1h : g_B0h;
    float* ssArr = g_ssH[zz];
    float* sdArr = g_sdH[zz];
    int tid = threadIdx.x;
    int lane = tid & 31, warp = tid >> 5;
    int ncol0 = halfN + warp * 16;

    // W fragments direct from transposed global
    const __half* Wt = g_Wt16 + (size_t)conv * EMB * EMB;
    unsigned bw[8][2][2];
    {
        int nf = ncol0 + (lane >> 2);
        int kf = (lane & 3) * 2;
        #pragma unroll
        for (int ks = 0; ks < 8; ks++)
            #pragma unroll
            for (int nt = 0; nt < 2; nt++) {
                const __half* p = Wt + (size_t)(nf + nt * 8) * EMB + ks * 16 + kf;
                bw[ks][nt][0] = *(const unsigned*)p;
                bw[ks][nt][1] = *(const unsigned*)(p + 8);
            }
    }

    const float* aS = asrc + (size_t)conv * EMB;
    const float* aD = adst + (size_t)conv * EMB;
    float w0s[2], w1s[2], w0d[2], w1d[2];
    #pragma unroll
    for (int nt = 0; nt < 2; nt++) {
        int col = ncol0 + nt * 8 + (lane & 3) * 2;
        w0s[nt] = aS[col]; w1s[nt] = aS[col + 1];
        w0d[nt] = aD[col]; w1d[nt] = aD[col + 1];
    }

    unsigned lbase = ((unsigned)((lane & 15) * BPAD + 8 * (lane >> 4))) * 2;

    auto cpA = [&](int tile, int b) {
        unsigned dbase = sbase + (unsigned)b * ABYTES;
        #pragma unroll
        for (int ii = 0; ii < 4; ii++) {
            int i = tid + ii * 128;                       // 0..511
            int r = i >> 4, c = i & 15;
            int row = tile * MT + r;
            if (row >= NN) row = 0;
            const __half* src = g_Ah + (size_t)row * EMB + c * 8;
            unsigned dst = dbase + (unsigned)(r * (BPAD * 2) + c * 16);
            cp16(dst, src);
        }
        asm volatile("cp.async.commit_group;" ::: "memory");
    };

    int tile = blockIdx.x;
    if (tile < NTILES) cpA(tile, 0);
    int nb = 1;
    for (; tile < NTILES; tile += GEMM_GRID_X) {
        int nxt = tile + GEMM_GRID_X;
        int cb = nb ^ 1;
        if (nxt < NTILES) {
            cpA(nxt, nb);
            asm volatile("cp.async.wait_group 1;" ::: "memory");
        } else {
            asm volatile("cp.async.wait_group 0;" ::: "memory");
        }
        __syncthreads();

        unsigned aAh = sbase + (unsigned)cb * ABYTES + lbase;

        float c[2][2][4];
        #pragma unroll
        for (int mb = 0; mb < 2; mb++)
            #pragma unroll
            for (int nt = 0; nt < 2; nt++)
                #pragma unroll
                for (int j = 0; j < 4; j++) c[mb][nt][j] = 0.f;

        #pragma unroll
        for (int ks = 0; ks < 8; ks++) {
            int k0 = ks * 16;
            unsigned ah[2][4];
            #pragma unroll
            for (int mb = 0; mb < 2; mb++)
                ldm4(ah[mb], aAh + (unsigned)(mb * 16 * BPAD + k0) * 2);
            #pragma unroll
            for (int nt = 0; nt < 2; nt++)
                #pragma unroll
                for (int mb = 0; mb < 2; mb++)
                    mma_f16(c[mb][nt], ah[mb], bw[ks][nt][0], bw[ks][nt][1]);
        }

        int row0 = tile * MT;
        #pragma unroll
        for (int mb = 0; mb < 2; mb++) {
            int rA = row0 + mb * 16 + (lane >> 2);
            int rB = rA + 8;
            float sAs = 0.f, sAd = 0.f, sBs = 0.f, sBd = 0.f;
            #pragma unroll
            for (int nt = 0; nt < 2; nt++) {
                int col = ncol0 + nt * 8 + (lane & 3) * 2;
                sAs += c[mb][nt][0] * w0s[nt] + c[mb][nt][1] * w1s[nt];
                sAd += c[mb][nt][0] * w0d[nt] + c[mb][nt][1] * w1d[nt];
                sBs += c[mb][nt][2] * w0s[nt] + c[mb][nt][3] * w1s[nt];
                sBd += c[mb][nt][2] * w0d[nt] + c[mb][nt][3] * w1d[nt];
                if (rA < NN) *(__half2*)&Bout[(size_t)rA * EMB + col] =
                    __floats2half2_rn(c[mb][nt][0], c[mb][nt][1]);
                if (rB < NN) *(__half2*)&Bout[(size_t)rB * EMB + col] =
                    __floats2half2_rn(c[mb][nt][2], c[mb][nt][3]);
            }
            #pragma unroll
            for (int o = 1; o <= 2; o <<= 1) {
                sAs += __shfl_xor_sync(0xffffffffu, sAs, o);
                sAd += __shfl_xor_sync(0xffffffffu, sAd, o);
                sBs += __shfl_xor_sync(0xffffffffu, sBs, o);
                sBd += __shfl_xor_sync(0xffffffffu, sBd, o);
            }
            if ((lane & 3) == 0) {
                int rloc = mb * 16 + (lane >> 2);
                sredS[warp * 32 + rloc] = sAs;
                sredD[warp * 32 + rloc] = sAd;
                sredS[warp * 32 + rloc + 8] = sBs;
                sredD[warp * 32 + rloc + 8] = sBd;
            }
        }
        __syncthreads();
        if (tid < 32) {
            int row = row0 + tid;
            if (row < NN) {
                ssArr[row] = sredS[tid] + sredS[32 + tid] + sredS[64 + tid] + sredS[96 + tid];
                sdArr[row] = sredD[tid] + sredD[32 + tid] + sredD[64 + tid] + sredD[96 + tid];
            }
        }
        nb ^= 1;
    }
}

// ---------------- fused softmax aggregation; partial-score sum; prefetch ----------
__global__ void aggregate_k(const int* __restrict__ node_type, const float* __restrict__ bias,
                            int convBase, const float* __restrict__ esc,
                            float* __restrict__ Out, __half* __restrict__ outH) {
    int g = blockIdx.x * blockDim.x + threadIdx.x;
    int v = g >> 5, lane = threadIdx.x & 31;
    if (v >= NN) return;
    bool user = (node_type[v] == 0);
    const __half* H   = user ? g_B1h : g_B0h;
    int p             = user ? 2 : 0;
    const float* ss0  = g_ssH[p];
    const float* ss1  = g_ssH[p + 1];
    float sd          = g_sdH[p][v] + g_sdH[p + 1][v];
    int conv          = convBase + (user ? 1 : 0);
    const float* bi   = bias + (size_t)conv * EMB;

    int beg = g_rowptr[v], end = g_rowptr[v + 1];
    float4 acc = make_float4(0.f, 0.f, 0.f, 0.f);
    float denom = 0.f;
    if (beg < end) {
        int s = (int)__ldg(&g_src16[beg]);
        float ec = __ldg(&esc[beg]);
        for (int i = beg; i < end; i++) {
            int sn = 0; float ecn = 0.f;
            if (i + 1 < end) {
                sn = (int)__ldg(&g_src16[i + 1]);
                ecn = __ldg(&esc[i + 1]);
            }
            float a = ss0[s] + ss1[s] + sd + ec;
            a = (a > 0.f) ? a : 0.2f * a;
            float w = __expf(a);
            denom += w;
            uint2 hv = *(const uint2*)(H + (size_t)s * EMB + lane * 4);
            float2 f0 = __half22float2(*(__half2*)&hv.x);
            float2 f1 = __half22float2(*(__half2*)&hv.y);
            acc.x = fmaf(w, f0.x, acc.x);
            acc.y = fmaf(w, f0.y, acc.y);
            acc.z = fmaf(w, f1.x, acc.z);
            acc.w = fmaf(w, f1.y, acc.w);
            s = sn; ec = ecn;
        }
    }
    float inv = 1.f / (denom + 1e-16f);
    float4 bv = ((const float4*)bi)[lane];
    float4 o;
    o.x = fmaxf(fmaf(acc.x, inv, bv.x), 0.f);
    o.y = fmaxf(fmaf(acc.y, inv, bv.y), 0.f);
    o.z = fmaxf(fmaf(acc.z, inv, bv.z), 0.f);
    o.w = fmaxf(fmaf(acc.w, inv, bv.w), 0.f);
    if (outH) {
        uint2 Hh;
        *(__half2*)&Hh.x = __floats2half2_rn(o.x, o.y);
        *(__half2*)&Hh.y = __floats2half2_rn(o.z, o.w);
        *(uint2*)&outH[(size_t)v * EMB + lane * 4] = Hh;
    } else {
        ((float4*)(Out + (size_t)v * EMB))[lane] = o;
    }
}

// ---------------- launch ----------------
extern "C" void kernel_launch(void* const* d_in, const int* in_sizes, int n_in,
                              void* d_out, int out_size) {
    const int*   node_ids  = (const int*)d_in[0];
    const int*   node_type = (const int*)d_in[1];
    const int*   edge_index= (const int*)d_in[2];
    const int*   edge_type = (const int*)d_in[3];
    const float* edge_attr = (const float*)d_in[4];
    const float* t         = (const float*)d_in[5];
    const float* emb       = (const float*)d_in[6];
    const float* timew     = (const float*)d_in[7];
    const float* timeb     = (const float*)d_in[8];
    const float* convW     = (const float*)d_in[9];
    const float* asrc      = (const float*)d_in[10];
    const float* adst      = (const float*)d_in[11];
    const float* eW        = (const float*)d_in[12];
    const float* aedge     = (const float*)d_in[13];
    const float* bias      = (const float*)d_in[14];
    float* out = (float*)d_out;

    __half* Ah_ptr = nullptr;
    cudaGetSymbolAddress((void**)&Ah_ptr, g_Ah);
    float* escA_ptr = nullptr;
    cudaGetSymbolAddress((void**)&escA_ptr, g_escA);
    float* escB_ptr = nullptr;
    cudaGetSymbolAddress((void**)&escB_ptr, g_escB);
    cudaFuncSetAttribute(gemm_mma_k, cudaFuncAttributeMaxDynamicSharedMemorySize, GEMM_SMEM);

    static cudaStream_t s2 = nullptr;
    static cudaEvent_t evFork = nullptr, evJoin = nullptr;
    if (!s2) {
        cudaStreamCreateWithFlags(&s2, cudaStreamNonBlocking);
        cudaEventCreateWithFlags(&evFork, cudaEventDisableTiming);
        cudaEventCreateWithFlags(&evJoin, cudaEventDisableTiming);
    }

    int nScanBlk = (NN + 1023) / 1024;  // 49
    int preGrid = (PRE_W64 + PRE_W + NN + 255) / 256;
    dim3 ggrid(GEMM_GRID_X, 1, 4);

    // 0: root
    precompute_k<<<preGrid, 256>>>(eW, aedge, convW);
    cudaEventRecord(evFork, 0);
    cudaStreamWaitEvent(s2, evFork, 0);

    // 1: hist (side arm start)
    hist_k<<<(NE + 255) / 256, 256, 0, s2>>>(edge_index, edge_type, node_type);
    // 2-3: main arm — gemm1 at launch index 3 for ncu
    splitA_emb_k<<<(NN * 32 + 255) / 256, 256>>>(node_ids, emb);
    gemm_mma_k<<<ggrid, 128, GEMM_SMEM>>>(asrc, adst, 0);
    // 4-5: rest of side arm
    scanF_k<<<nScanBlk, 1024, 0, s2>>>();
    scatter_k<<<(NE + 255) / 256, 256, 0, s2>>>(edge_index, edge_type, node_type,
                                                edge_attr, t, timew, timeb);
    cudaEventRecord(evJoin, s2);

    // join, serial tail
    cudaStreamWaitEvent(0, evJoin, 0);
    aggregate_k<<<(NN * 32 + 255) / 256, 256>>>(node_type, bias, 0, escA_ptr,
                                                nullptr, Ah_ptr);
    gemm_mma_k<<<ggrid, 128, GEMM_SMEM>>>(asrc, adst, 2);
    aggregate_k<<<(NN * 32 + 255) / 256, 256>>>(node_type, bias, 2, escB_ptr,
                                                out, nullptr);
}

// round 17
// speedup vs baseline: 1.2168x; 1.0655x over previous
#include <cuda_runtime.h>
#include <cuda_fp16.h>

#define NN 50000
#define NE 600000
#define EMB 128
#define TDIM 32
#define RAW 32

// ---------------- scratch (static device globals; no allocation) ----------------
static __device__ __align__(16) __half g_Ah[NN * EMB];   // A (fp16)
static __device__ __align__(16) __half g_B0h[NN * EMB];  // h (conv even), fp16
static __device__ __align__(16) __half g_B1h[NN * EMB];  // h (conv odd), fp16
static __device__ float g_w64[4 * 64];                   // eW @ a_edge per conv
static __device__ __align__(16) __half g_Wt16[4 * EMB * EMB];  // W fp16 TRANSPOSED [conv][n][k]
static __device__ int   g_deg[NN];
static __device__ int   g_rowptr[NN + 1];
static __device__ int   g_cur[NN];
static __device__ int   g_bsum[64];
static __device__ int   g_boff[64];
static __device__ int   g_scanCnt;
static __device__ volatile int g_scanFlag;
static __device__ unsigned short g_src16[NE];
static __device__ float g_escA[NE];
static __device__ float g_escB[NE];
// per (conv-parity, N-half) partial attention dots: z = parity*2 + half
static __device__ float g_ssH[4][NN];
static __device__ float g_sdH[4][NN];

// ---------------- PTX helpers ----------------
__device__ __forceinline__ unsigned smem_u32(const void* p) {
    unsigned r;
    asm("{ .reg .u64 t; cvta.to.shared.u64 t, %1; cvt.u32.u64 %0, t; }" : "=r"(r) : "l"(p));
    return r;
}
__device__ __forceinline__ void ldm4(unsigned* r, unsigned addr) {
    asm volatile("ldmatrix.sync.aligned.m8n8.x4.shared.b16 {%0,%1,%2,%3}, [%4];"
                 : "=r"(r[0]), "=r"(r[1]), "=r"(r[2]), "=r"(r[3]) : "r"(addr));
}
__device__ __forceinline__ void mma_f16(float* c, const unsigned* a, unsigned b0, unsigned b1) {
    asm volatile("mma.sync.aligned.m16n8k16.row.col.f32.f16.f16.f32 "
                 "{%0,%1,%2,%3}, {%4,%5,%6,%7}, {%8,%9}, {%0,%1,%2,%3};"
                 : "+f"(c[0]), "+f"(c[1]), "+f"(c[2]), "+f"(c[3])
                 : "r"(a[0]), "r"(a[1]), "r"(a[2]), "r"(a[3]), "r"(b0), "r"(b1));
}
__device__ __forceinline__ void cp16(unsigned dst, const void* src) {
    asm volatile("cp.async.cg.shared.global [%0], [%1], 16;" :: "r"(dst), "l"(src));
}

// ---------------- root kernel: w64 + fp16 W^T + zero + A gather/convert ----------
#define PRE_W64 256
#define PRE_W (4 * EMB * EMB)
#define PRE_Z (PRE_W64 + PRE_W + NN)
__global__ void precompute_k(const float* __restrict__ eW, const float* __restrict__ aedge,
                             const float* __restrict__ W,
                             const int* __restrict__ ids, const float* __restrict__ emb) {
    int idx = blockIdx.x * blockDim.x + threadIdx.x;
    if (idx == 0) { g_scanCnt = 0; g_scanFlag = 0; }
    if (idx < PRE_W64) {
        int c = idx >> 6, j = idx & 63;
        const float* ew = eW + (c * 64 + j) * EMB;
        const float* ae = aedge + c * EMB;
        float s = 0.f;
        #pragma unroll 8
        for (int f = 0; f < EMB; f++) s = fmaf(ew[f], ae[f], s);
        g_w64[idx] = s;
    } else if (idx < PRE_W64 + PRE_W) {
        int i = idx - PRE_W64;
        int c = i >> 14, rem = i & 16383;
        int n = rem >> 7, k = rem & 127;
        g_Wt16[i] = __float2half_rn(W[c * 16384 + k * 128 + n]);   // transpose
    } else if (idx < PRE_Z) {
        int i = idx - PRE_W64 - PRE_W;
        g_deg[i] = 0; g_cur[i] = 0;
    } else {
        int i = idx - PRE_Z;
        if (i < NN * 32) {
            int v = i >> 5, c = i & 31;
            float4 x = ((const float4*)emb)[(size_t)__ldg(&ids[v]) * 32 + c];
            uint2 H;
            *(__half2*)&H.x = __floats2half2_rn(x.x, x.y);
            *(__half2*)&H.y = __floats2half2_rn(x.z, x.w);
            *(uint2*)&g_Ah[(size_t)v * EMB + c * 4] = H;
        }
    }
}

// ---------------- CSR build (only edges whose type matches dst's node type) ------
__global__ void hist_k(const int* __restrict__ ei, const int* __restrict__ etype,
                       const int* __restrict__ ntype) {
    int e = blockIdx.x * blockDim.x + threadIdx.x;
    if (e >= NE) return;
    int dst = ei[NE + e];
    int req = (__ldg(&ntype[dst]) == 0) ? 1 : 0;
    if (etype[e] == req) atomicAdd(&g_deg[dst], 1);
}

// fused scan (49 co-resident blocks)
__global__ void scanF_k() {
    __shared__ int ws[32];
    __shared__ int s_last;
    int tid = threadIdx.x, lane = tid & 31, wid = tid >> 5;
    int i = blockIdx.x * 1024 + tid;
    int v = (i < NN) ? g_deg[i] : 0;
    int x = v;
    #pragma unroll
    for (int o = 1; o < 32; o <<= 1) {
        int y = __shfl_up_sync(0xffffffffu, x, o);
        if (lane >= o) x += y;
    }
    if (lane == 31) ws[wid] = x;
    __syncthreads();
    if (wid == 0) {
        int s = ws[lane];
        #pragma unroll
        for (int o = 1; o < 32; o <<= 1) {
            int y = __shfl_up_sync(0xffffffffu, s, o);
            if (lane >= o) s += y;
        }
        ws[lane] = s;
    }
    __syncthreads();
    int incl = x + (wid > 0 ? ws[wid - 1] : 0);
    int myexc = incl - v;
    if (tid == 1023) g_bsum[blockIdx.x] = incl;
    __threadfence();
    if (tid == 0) s_last = (atomicAdd(&g_scanCnt, 1) == (int)gridDim.x - 1);
    __syncthreads();
    if (s_last) {
        int bv = 0, bx = 0;
        if (tid < 64) {
            bv = (tid < (int)gridDim.x) ? g_bsum[tid] : 0;
            bx = bv;
            #pragma unroll
            for (int o = 1; o < 32; o <<= 1) {
                int y = __shfl_up_sync(0xffffffffu, bx, o);
                if (lane >= o) bx += y;
            }
            if (lane == 31) ws[wid] = bx;
        }
        __syncthreads();
        if (tid < 64) {
            int incl2 = bx + (tid >= 32 ? ws[0] : 0);
            g_boff[tid] = incl2 - bv;
            if (tid == 63) g_rowptr[NN] = incl2;
        }
        __threadfence();
        __syncthreads();
        if (tid == 0) g_scanFlag = 1;
    }
    if (tid == 0) {
        while (g_scanFlag == 0) __nanosleep(64);
    }
    __syncthreads();
    __threadfence();
    if (i < NN) g_rowptr[i] = myexc + g_boff[blockIdx.x];
}

__global__ void scatter_k(const int* __restrict__ ei, const int* __restrict__ etype,
                          const int* __restrict__ ntype,
                          const float* __restrict__ eattr, const float* __restrict__ t,
                          const float* __restrict__ timew, const float* __restrict__ timeb) {
    int e = blockIdx.x * blockDim.x + threadIdx.x;
    if (e >= NE) return;
    int dst = ei[NE + e];
    int user = (__ldg(&ntype[dst]) == 0) ? 1 : 0;
    if (etype[e] != user) return;
    int src = ei[e];
    int pos = g_rowptr[dst] + atomicAdd(&g_cur[dst], 1);
    g_src16[pos] = (unsigned short)src;

    const float* w1 = g_w64 + user * 64;
    const float* w2 = g_w64 + (2 + user) * 64;
    float tv = t[e];
    float e1 = 0.f, e2 = 0.f;
    #pragma unroll 8
    for (int j = 0; j < TDIM; j++) {
        float te = __cosf(fmaf(tv, timew[j], timeb[j]));
        e1 = fmaf(te, w1[j], e1);
        e2 = fmaf(te, w2[j], e2);
    }
    const float4* ar = (const float4*)(eattr + (size_t)e * RAW);
    #pragma unroll
    for (int q = 0; q < 8; q++) {
        float4 av = ar[q];
        int j = 32 + q * 4;
        e1 = fmaf(av.x, w1[j], e1);     e1 = fmaf(av.y, w1[j + 1], e1);
        e1 = fmaf(av.z, w1[j + 2], e1); e1 = fmaf(av.w, w1[j + 3], e1);
        e2 = fmaf(av.x, w2[j], e2);     e2 = fmaf(av.y, w2[j + 1], e2);
        e2 = fmaf(av.z, w2[j + 2], e2); e2 = fmaf(av.w, w2[j + 3], e2);
    }
    g_escA[pos] = e1;
    g_escB[pos] = e2;
}

// ---------------- persistent fp16 GEMM, 5 CTAs/SM, coalesced epilogue -------------
// grid (185,1,4): z = (conv, N-half). CTA: 128 threads, tile M=32 x N=64.
// Epilogue stages H into the freed A-buffer (144B row stride, conflict-free STS),
// then writes 32 rows x 128B via coalesced uint4 STG.
#define BPAD 136
#define MT 32
#define NTILES ((NN + MT - 1) / MT)    // 1563
#define GEMM_GRID_X 185                // x4 z -> 740 CTAs -> 5/SM
#define ABYTES (MT * BPAD * 2)         // 8704
#define STG_STRIDE 72                  // halfs; 144B row stride (staging fits in ABYTES)
#define SMEM_RED_OFF (2 * ABYTES)
#define GEMM_SMEM (2 * ABYTES + 1280)

__global__ void __launch_bounds__(128, 5) gemm_mma_k(const float* __restrict__ asrc,
                                                     const float* __restrict__ adst,
                                                     int convBase) {
    extern __shared__ __align__(16) char smraw[];
    float* sredS = (float*)(smraw + SMEM_RED_OFF);        // [4][32]
    float* sredD = sredS + 128;                           // [4][32]
    unsigned sbase = smem_u32(smraw);

    int zz = blockIdx.z;
    int conv = convBase + (zz >> 1);
    int halfN = (zz & 1) * 64;
    __half* Bout = (zz >> 1) ? g_B1h : g_B0h;
    float* ssArr = g_ssH[zz];
    float* sdArr = g_sdH[zz];
    int tid = threadIdx.x;
    int lane = tid & 31, warp = tid >> 5;
    int ncol0 = halfN + warp * 16;

    // W fragments direct from transposed global
    const __half* Wt = g_Wt16 + (size_t)conv * EMB * EMB;
    unsigned bw[8][2][2];
    {
        int nf = ncol0 + (lane >> 2);
        int kf = (lane & 3) * 2;
        #pragma unroll
        for (int ks = 0; ks < 8; ks++)
            #pragma unroll
            for (int nt = 0; nt < 2; nt++) {
                const __half* p = Wt + (size_t)(nf + nt * 8) * EMB + ks * 16 + kf;
                bw[ks][nt][0] = *(const unsigned*)p;
                bw[ks][nt][1] = *(const unsigned*)(p + 8);
            }
    }

    const float* aS = asrc + (size_t)conv * EMB;
    const float* aD = adst + (size_t)conv * EMB;
    float w0s[2], w1s[2], w0d[2], w1d[2];
    #pragma unroll
    for (int nt = 0; nt < 2; nt++) {
        int col = ncol0 + nt * 8 + (lane & 3) * 2;
        w0s[nt] = aS[col]; w1s[nt] = aS[col + 1];
        w0d[nt] = aD[col]; w1d[nt] = aD[col + 1];
    }

    unsigned lbase = ((unsigned)((lane & 15) * BPAD + 8 * (lane >> 4))) * 2;

    auto cpA = [&](int tile, int b) {
        unsigned dbase = sbase + (unsigned)b * ABYTES;
        #pragma unroll
        for (int ii = 0; ii < 4; ii++) {
            int i = tid + ii * 128;                       // 0..511
            int r = i >> 4, c = i & 15;
            int row = tile * MT + r;
            if (row >= NN) row = 0;
            const __half* src = g_Ah + (size_t)row * EMB + c * 8;
            unsigned dst = dbase + (unsigned)(r * (BPAD * 2) + c * 16);
            cp16(dst, src);
        }
        asm volatile("cp.async.commit_group;" ::: "memory");
    };

    int tile = blockIdx.x;
    if (tile < NTILES) cpA(tile, 0);
    int nb = 1;
    for (; tile < NTILES; tile += GEMM_GRID_X) {
        int nxt = tile + GEMM_GRID_X;
        int cb = nb ^ 1;
        if (nxt < NTILES) {
            cpA(nxt, nb);
            asm volatile("cp.async.wait_group 1;" ::: "memory");
        } else {
            asm volatile("cp.async.wait_group 0;" ::: "memory");
        }
        __syncthreads();

        unsigned aAh = sbase + (unsigned)cb * ABYTES + lbase;

        float c[2][2][4];
        #pragma unroll
        for (int mb = 0; mb < 2; mb++)
            #pragma unroll
            for (int nt = 0; nt < 2; nt++)
                #pragma unroll
                for (int j = 0; j < 4; j++) c[mb][nt][j] = 0.f;

        #pragma unroll
        for (int ks = 0; ks < 8; ks++) {
            int k0 = ks * 16;
            unsigned ah[2][4];
            #pragma unroll
            for (int mb = 0; mb < 2; mb++)
                ldm4(ah[mb], aAh + (unsigned)(mb * 16 * BPAD + k0) * 2);
            #pragma unroll
            for (int nt = 0; nt < 2; nt++)
                #pragma unroll
                for (int mb = 0; mb < 2; mb++)
                    mma_f16(c[mb][nt], ah[mb], bw[ks][nt][0], bw[ks][nt][1]);
        }
        __syncthreads();   // all warps done reading A[cb] before staging reuses it

        // stage into freed A[cb] buffer (conflict-free: 36-word row stride)
        __half* stg = (__half*)(smraw + (unsigned)cb * ABYTES);
        int row0 = tile * MT;
        #pragma unroll
        for (int mb = 0; mb < 2; mb++) {
            int rloc = mb * 16 + (lane >> 2);
            float sAs = 0.f, sAd = 0.f, sBs = 0.f, sBd = 0.f;
            #pragma unroll
            for (int nt = 0; nt < 2; nt++) {
                int colL = warp * 16 + nt * 8 + (lane & 3) * 2;   // 0..63 local
                float w0sv = w0s[nt], w1sv = w1s[nt], w0dv = w0d[nt], w1dv = w1d[nt];
                sAs += c[mb][nt][0] * w0sv + c[mb][nt][1] * w1sv;
                sAd += c[mb][nt][0] * w0dv + c[mb][nt][1] * w1dv;
                sBs += c[mb][nt][2] * w0sv + c[mb][nt][3] * w1sv;
                sBd += c[mb][nt][2] * w0dv + c[mb][nt][3] * w1dv;
                *(__half2*)&stg[rloc * STG_STRIDE + colL] =
                    __floats2half2_rn(c[mb][nt][0], c[mb][nt][1]);
                *(__half2*)&stg[(rloc + 8) * STG_STRIDE + colL] =
                    __floats2half2_rn(c[mb][nt][2], c[mb][nt][3]);
            }
            #pragma unroll
            for (int o = 1; o <= 2; o <<= 1) {
                sAs += __shfl_xor_sync(0xffffffffu, sAs, o);
                sAd += __shfl_xor_sync(0xffffffffu, sAd, o);
                sBs += __shfl_xor_sync(0xffffffffu, sBs, o);
                sBd += __shfl_xor_sync(0xffffffffu, sBd, o);
            }
            if ((lane & 3) == 0) {
                int rr = mb * 16 + (lane >> 2);
                sredS[warp * 32 + rr] = sAs;
                sredD[warp * 32 + rr] = sAd;
                sredS[warp * 32 + rr + 8] = sBs;
                sredD[warp * 32 + rr + 8] = sBd;
            }
        }
        __syncthreads();

        // coalesced H store: 32 rows x 64 halfs (128B) each
        #pragma unroll
        for (int i2 = 0; i2 < 2; i2++) {
            int i = tid + i2 * 128;                       // 0..255
            int r = i >> 3, q = i & 7;
            int row = row0 + r;
            if (row < NN) {
                uint4 v = *(uint4*)&stg[r * STG_STRIDE + q * 8];
                *(uint4*)&Bout[(size_t)row * EMB + halfN + q * 8] = v;
            }
        }
        if (tid < 32) {
            int row = row0 + tid;
            if (row < NN) {
                ssArr[row] = sredS[tid] + sredS[32 + tid] + sredS[64 + tid] + sredS[96 + tid];
                sdArr[row] = sredD[tid] + sredD[32 + tid] + sredD[64 + tid] + sredD[96 + tid];
            }
        }
        __syncthreads();   // staging reads done before next cpA overwrites it
        nb ^= 1;
    }
}

// ---------------- fused softmax aggregation; partial-score sum; prefetch ----------
__global__ void aggregate_k(const int* __restrict__ node_type, const float* __restrict__ bias,
                            int convBase, const float* __restrict__ esc,
                            float* __restrict__ Out, __half* __restrict__ outH) {
    int g = blockIdx.x * blockDim.x + threadIdx.x;
    int v = g >> 5, lane = threadIdx.x & 31;
    if (v >= NN) return;
    bool user = (node_type[v] == 0);
    const __half* H   = user ? g_B1h : g_B0h;
    int p             = user ? 2 : 0;
    const float* ss0  = g_ssH[p];
    const float* ss1  = g_ssH[p + 1];
    float sd          = g_sdH[p][v] + g_sdH[p + 1][v];
    int conv          = convBase + (user ? 1 : 0);
    const float* bi   = bias + (size_t)conv * EMB;

    int beg = g_rowptr[v], end = g_rowptr[v + 1];
    float4 acc = make_float4(0.f, 0.f, 0.f, 0.f);
    float denom = 0.f;
    if (beg < end) {
        int s = (int)__ldg(&g_src16[beg]);
        float ec = __ldg(&esc[beg]);
        for (int i = beg; i < end; i++) {
            int sn = 0; float ecn = 0.f;
            if (i + 1 < end) {
                sn = (int)__ldg(&g_src16[i + 1]);
                ecn = __ldg(&esc[i + 1]);
            }
            float a = ss0[s] + ss1[s] + sd + ec;
            a = (a > 0.f) ? a : 0.2f * a;
            float w = __expf(a);
            denom += w;
            uint2 hv = *(const uint2*)(H + (size_t)s * EMB + lane * 4);
            float2 f0 = __half22float2(*(__half2*)&hv.x);
            float2 f1 = __half22float2(*(__half2*)&hv.y);
            acc.x = fmaf(w, f0.x, acc.x);
            acc.y = fmaf(w, f0.y, acc.y);
            acc.z = fmaf(w, f1.x, acc.z);
            acc.w = fmaf(w, f1.y, acc.w);
            s = sn; ec = ecn;
        }
    }
    float inv = 1.f / (denom + 1e-16f);
    float4 bv = ((const float4*)bi)[lane];
    float4 o;
    o.x = fmaxf(fmaf(acc.x, inv, bv.x), 0.f);
    o.y = fmaxf(fmaf(acc.y, inv, bv.y), 0.f);
    o.z = fmaxf(fmaf(acc.z, inv, bv.z), 0.f);
    o.w = fmaxf(fmaf(acc.w, inv, bv.w), 0.f);
    if (outH) {
        uint2 Hh;
        *(__half2*)&Hh.x = __floats2half2_rn(o.x, o.y);
        *(__half2*)&Hh.y = __floats2half2_rn(o.z, o.w);
        *(uint2*)&outH[(size_t)v * EMB + lane * 4] = Hh;
    } else {
        ((float4*)(Out + (size_t)v * EMB))[lane] = o;
    }
}

// ---------------- launch ----------------
extern "C" void kernel_launch(void* const* d_in, const int* in_sizes, int n_in,
                              void* d_out, int out_size) {
    const int*   node_ids  = (const int*)d_in[0];
    const int*   node_type = (const int*)d_in[1];
    const int*   edge_index= (const int*)d_in[2];
    const int*   edge_type = (const int*)d_in[3];
    const float* edge_attr = (const float*)d_in[4];
    const float* t         = (const float*)d_in[5];
    const float* emb       = (const float*)d_in[6];
    const float* timew     = (const float*)d_in[7];
    const float* timeb     = (const float*)d_in[8];
    const float* convW     = (const float*)d_in[9];
    const float* asrc      = (const float*)d_in[10];
    const float* adst      = (const float*)d_in[11];
    const float* eW        = (const float*)d_in[12];
    const float* aedge     = (const float*)d_in[13];
    const float* bias      = (const float*)d_in[14];
    float* out = (float*)d_out;

    __half* Ah_ptr = nullptr;
    cudaGetSymbolAddress((void**)&Ah_ptr, g_Ah);
    float* escA_ptr = nullptr;
    cudaGetSymbolAddress((void**)&escA_ptr, g_escA);
    float* escB_ptr = nullptr;
    cudaGetSymbolAddress((void**)&escB_ptr, g_escB);
    cudaFuncSetAttribute(gemm_mma_k, cudaFuncAttributeMaxDynamicSharedMemorySize, GEMM_SMEM);

    static cudaStream_t s2 = nullptr;
    static cudaEvent_t evFork = nullptr, evJoin = nullptr;
    if (!s2) {
        cudaStreamCreateWithFlags(&s2, cudaStreamNonBlocking);
        cudaEventCreateWithFlags(&evFork, cudaEventDisableTiming);
        cudaEventCreateWithFlags(&evJoin, cudaEventDisableTiming);
    }

    int nScanBlk = (NN + 1023) / 1024;  // 49
    int preGrid = (PRE_Z + NN * 32 + 255) / 256;
    dim3 ggrid(GEMM_GRID_X, 1, 4);

    // 0: root (w64 + W^T + zero + A gather)
    precompute_k<<<preGrid, 256>>>(eW, aedge, convW, node_ids, emb);
    cudaEventRecord(evFork, 0);
    cudaStreamWaitEvent(s2, evFork, 0);

    // 1-2: side arm start
    hist_k<<<(NE + 255) / 256, 256, 0, s2>>>(edge_index, edge_type, node_type);
    scanF_k<<<nScanBlk, 1024, 0, s2>>>();
    // 3: gemm1 (ncu sample slot)
    gemm_mma_k<<<ggrid, 128, GEMM_SMEM>>>(asrc, adst, 0);
    // 4: rest of side arm
    scatter_k<<<(NE + 255) / 256, 256, 0, s2>>>(edge_index, edge_type, node_type,
                                                edge_attr, t, timew, timeb);
    cudaEventRecord(evJoin, s2);

    // join, serial tail
    cudaStreamWaitEvent(0, evJoin, 0);
    aggregate_k<<<(NN * 32 + 255) / 256, 256>>>(node_type, bias, 0, escA_ptr,
                                                nullptr, Ah_ptr);
    gemm_mma_k<<<ggrid, 128, GEMM_SMEM>>>(asrc, adst, 2);
    aggregate_k<<<(NN * 32 + 255) / 256, 256>>>(node_type, bias, 2, escB_ptr,
                                                out, nullptr);
}